// round 7
// baseline (speedup 1.0000x reference)
#include <cuda_runtime.h>

typedef unsigned int u32;

// CostVolume via banded tf32 GEMM (mma.sync m16n8k8), single-phase smem.
// Block = (bh, 128-w tile), 256 threads / 8 warps.
// Warp wid: G[16,80] = L[rows 16wid..+15, 0..63] . R[rows 16wid..+79, 0..63]^T
// (R row r <-> src = w0-64+r), out[w,d] = G[w_l, w_l+63-d]/64, masked src<0.

namespace {
constexpr int Wd = 512, Cd = 64, Dd = 64, WT = 128;
constexpr int P        = 72;              // smem pitch (words), all 64 channels
constexpr int LS_WORDS = 128 * P;         // 9216
constexpr int RS_WORDS = 192 * P;         // 13824
constexpr int SMEM_BYTES = (LS_WORDS + RS_WORDS) * 4;   // 92,160
constexpr int STG_P    = 68;              // staging pitch (words)
}

__device__ __forceinline__ u32 f2tf32(float x) {
    u32 r;
    asm("cvt.rna.tf32.f32 %0, %1;" : "=r"(r) : "f"(x));
    return r;
}
__device__ __forceinline__ void mma_tf32(float* d, const u32* a, u32 b0, u32 b1) {
    asm("mma.sync.aligned.m16n8k8.row.col.f32.tf32.tf32.f32 "
        "{%0,%1,%2,%3}, {%4,%5,%6,%7}, {%8,%9}, {%0,%1,%2,%3};"
        : "+f"(d[0]), "+f"(d[1]), "+f"(d[2]), "+f"(d[3])
        : "r"(a[0]), "r"(a[1]), "r"(a[2]), "r"(a[3]), "r"(b0), "r"(b1));
}

__global__ __launch_bounds__(256, 2)
void cost_volume_mma_kernel(const float* __restrict__ left,
                            const float* __restrict__ right,
                            float* __restrict__ out) {
    extern __shared__ u32 sm[];
    u32* Ls = sm;                 // [w_local 0..127][c 0..63], pitch P
    u32* Rs = sm + LS_WORDS;      // [s_local 0..191][c 0..63], pitch P

    const int tid  = threadIdx.x;
    const int wid  = tid >> 5;        // 0..7
    const int lane = tid & 31;
    const int q    = lane >> 2;       // 0..7
    const int c    = lane & 3;        // 0..3
    const int w0   = blockIdx.x * WT;
    const int bh   = blockIdx.y;

    const float* lrow = left  + (size_t)bh * Wd * Cd;
    const float* rrow = right + (size_t)bh * Wd * Cd;

    // ---- single fill: all 64 channels, tf32-converted ----
#pragma unroll
    for (int i = 0; i < 8; i++) {
        const int idx = tid + 256 * i;          // 0..2047
        const int row = idx >> 4, c4 = idx & 15;
        const float4 v = *(const float4*)(lrow + (size_t)(w0 + row) * Cd + 4 * c4);
        uint4 t = make_uint4(f2tf32(v.x), f2tf32(v.y), f2tf32(v.z), f2tf32(v.w));
        *(uint4*)&Ls[row * P + 4 * c4] = t;
    }
#pragma unroll
    for (int i = 0; i < 12; i++) {
        const int idx = tid + 256 * i;          // 0..3071
        const int row = idx >> 4, c4 = idx & 15;
        const int s = max(w0 - 64 + row, 0);    // clamped; masked later
        const float4 v = *(const float4*)(rrow + (size_t)s * Cd + 4 * c4);
        uint4 t = make_uint4(f2tf32(v.x), f2tf32(v.y), f2tf32(v.z), f2tf32(v.w));
        *(uint4*)&Rs[row * P + 4 * c4] = t;
    }
    __syncthreads();

    // ---- compute: 8 K-steps of 8 (k-permuted fragments via v2 loads) ----
    float acc[10][4];
#pragma unroll
    for (int nt = 0; nt < 10; nt++)
#pragma unroll
        for (int r = 0; r < 4; r++) acc[nt][r] = 0.0f;

    const u32* la_base = &Ls[(16 * wid + q) * P];
    const u32* rb_base = &Rs[(16 * wid + q) * P];
#pragma unroll
    for (int ks = 0; ks < 8; ks++) {
        const int kb = 8 * ks + 2 * c;
        u32 a[4];
        {
            const uint2 lo = *(const uint2*)(la_base + kb);
            const uint2 hi = *(const uint2*)(la_base + 8 * P + kb);
            a[0] = lo.x; a[2] = lo.y; a[1] = hi.x; a[3] = hi.y;
        }
#pragma unroll
        for (int nt = 0; nt < 10; nt++) {
            const uint2 bb = *(const uint2*)(rb_base + (8 * nt) * P + kb);
            mma_tf32(acc[nt], a, bb.x, bb.y);
        }
    }

    // ---- epilogue: diagonal extraction into smem staging ----
    __syncthreads();
    float* stage = (float*)sm;                    // [128][STG_P]
    const float scale = 1.0f / 64.0f;
#pragma unroll
    for (int nt = 0; nt < 10; nt++)
#pragma unroll
        for (int r = 0; r < 4; r++) {
            const int d = 63 + q + 8 * (r >> 1) - 8 * nt - 2 * c - (r & 1);
            if (d >= 0 && d < 64) {
                const int w_l = 16 * wid + q + 8 * (r >> 1);
                const int s_l = w_l + 63 - d;
                const float val = (w0 + s_l >= 64) ? acc[nt][r] * scale : 0.0f;
                stage[w_l * STG_P + d] = val;
            }
        }
    __syncthreads();

    // ---- coalesced copy staging -> gmem ----
#pragma unroll
    for (int i = 0; i < 8; i++) {
        const int idx = tid + 256 * i;           // 0..2047
        const int row = idx >> 4, c4 = idx & 15;
        const float4 v = *(const float4*)(stage + row * STG_P + 4 * c4);
        *(float4*)(out + ((size_t)bh * Wd + w0 + row) * Dd + 4 * c4) = v;
    }
}

extern "C" void kernel_launch(void* const* d_in, const int* in_sizes, int n_in,
                              void* d_out, int out_size) {
    const float* left  = (const float*)d_in[0];
    const float* right = (const float*)d_in[1];
    float* outp = (float*)d_out;

    const int BH = in_sizes[0] / (Wd * Cd);

    cudaFuncSetAttribute(cost_volume_mma_kernel,
                         cudaFuncAttributeMaxDynamicSharedMemorySize, SMEM_BYTES);
    dim3 grid(Wd / WT, BH, 1);
    cost_volume_mma_kernel<<<grid, 256, SMEM_BYTES>>>(left, right, outp);
}